// round 11
// baseline (speedup 1.0000x reference)
#include <cuda_runtime.h>
#include <cuda_fp16.h>

// ---------------------------------------------------------------------------
// BlocCircLinear via mma.sync m16n8k16 (f16 in / f32 acc), compute_103-safe.
//   D[b=32, 8192] = X[32, 8192] @ W^T,  W block-circulant from blocks[512][16][16].
// R11: 2 co-resident CTAs/SM for phase overlap. Evidence: bc_mma is ~19us
//   wall with only ~10.6us tensor-busy; the serial staging prologue and
//   epilogue are exposed because one 116KB-smem CTA owns each SM. Halve the
//   CTA (K=512, 256 thr, 65.5KB smem, <=128 regs) -> 256 CTAs, 2/SM: one
//   CTA's staging/epilogue overlaps the other's MMA mainloop.
//   Mainloop identical to the proven R10 inner loop (window 63 blocks).
// ---------------------------------------------------------------------------

#define BATCH   32
#define NBLK    512
#define DIM     8192
#define NTILES  16        // 8192 / 512 output cols
#define KSPLIT  16        // K split across CTAs -> 512 per CTA
#define JSTEPS  32        // 512 / 16
#define THREADS 256
#define PSZ     (BATCH * DIM)

#define XS_STR   520                        // halves per x row (512 + 8 pad)
#define BLK_N    63                         // blocks staged per CTA
#define PAD_LO   512                        // underflow pad (B prefetch d = -1)
#define PAD_HI   1024                       // overflow pad (A prefetch @ last j)
#define OFF_BLK  PAD_LO
#define OFF_XS   (PAD_LO + BLK_N * 512)     // 512 + 32256 = 32768
#define SMEM_TOT (OFF_XS + BATCH * XS_STR * 2 + PAD_HI)   // 67072

__device__ __half g_parth[KSPLIT * PSZ];    // f16 partials [16][32][8192], 8 MB

static __device__ __forceinline__ unsigned swzb(unsigned off) {
    return off ^ ((off >> 3) & 0x70);
}
static __device__ __forceinline__ unsigned smem_u32(const void* p) {
    return (unsigned)__cvta_generic_to_shared(p);
}
static __device__ __forceinline__ void ldsm4(unsigned* r, unsigned addr) {
    asm volatile("ldmatrix.sync.aligned.m8n8.x4.shared.b16 {%0,%1,%2,%3}, [%4];"
                 : "=r"(r[0]), "=r"(r[1]), "=r"(r[2]), "=r"(r[3]) : "r"(addr));
}
static __device__ __forceinline__ void mma16816(float* c, const unsigned* a,
                                                unsigned b0, unsigned b1) {
    asm volatile(
        "mma.sync.aligned.m16n8k16.row.col.f32.f16.f16.f32 "
        "{%0,%1,%2,%3}, {%4,%5,%6,%7}, {%8,%9}, {%0,%1,%2,%3};"
        : "+f"(c[0]), "+f"(c[1]), "+f"(c[2]), "+f"(c[3])
        : "r"(a[0]), "r"(a[1]), "r"(a[2]), "r"(a[3]), "r"(b0), "r"(b1));
}
static __device__ __forceinline__ uint4 cvt8(float4 a, float4 b) {
    __half2 h0 = __float22half2_rn(make_float2(a.x, a.y));
    __half2 h1 = __float22half2_rn(make_float2(a.z, a.w));
    __half2 h2 = __float22half2_rn(make_float2(b.x, b.y));
    __half2 h3 = __float22half2_rn(make_float2(b.z, b.w));
    uint4 o;
    o.x = *reinterpret_cast<unsigned*>(&h0);
    o.y = *reinterpret_cast<unsigned*>(&h1);
    o.z = *reinterpret_cast<unsigned*>(&h2);
    o.w = *reinterpret_cast<unsigned*>(&h3);
    return o;
}

// ---------------------------------------------------------------------------
// Kernel 1: block-circulant GEMM with fused f32->f16 staging.
// grid = NTILES * KSPLIT = 256 CTAs x 256 threads, 2 CTAs/SM resident.
// ---------------------------------------------------------------------------
extern __shared__ __align__(1024) char smem[];

__global__ void __launch_bounds__(THREADS, 2) bc_mma_kernel(
    const float* __restrict__ x32, const float* __restrict__ blk32)
{
    const int tid  = threadIdx.x;
    const int wid  = tid >> 5;
    const int lane = tid & 31;
    const int grp  = wid;                     // col-group 0..7
    const int T    = blockIdx.x & (NTILES - 1);
    const int ks   = blockIdx.x >> 4;         // 0..15
    const int smin = (T * 32 - ks * 32 - 31) & (NBLK - 1);

    char* blk = smem + OFF_BLK;
    char* xsb = smem + OFF_XS;

    // ---- stage + convert: x chunk (32 x 512 f32) and 63 blocks ----
    {
        const float4* xf = reinterpret_cast<const float4*>(x32);
#pragma unroll
        for (int i = tid; i < 2048; i += THREADS) {   // 16B-half chunks
            int row = i >> 6, cc = i & 63;
            // row stride 8192 f32 = 2048 f4; CTA K range 512 f32 = 128 f4.
            const float4* p = xf + row * 2048 + ks * 128 + cc * 2;
            float4 a = p[0], b = p[1];
            *reinterpret_cast<uint4*>(xsb + row * (XS_STR * 2) + cc * 16) =
                cvt8(a, b);
        }
        const float4* bf = reinterpret_cast<const float4*>(blk32);
#pragma unroll
        for (int i = tid; i < BLK_N * 32; i += THREADS) {
            int d = i >> 5, w = i & 31;
            int s = (smin + d) & (NBLK - 1);
            const float4* p = bf + s * 64 + w * 2;
            float4 a = p[0], b = p[1];
            *reinterpret_cast<uint4*>(blk + d * 512 + swzb(w * 16)) =
                cvt8(a, b);
        }
        __syncthreads();
    }

    // ---- lane-invariant ldmatrix addresses ----
    const int a0 = grp * 4;                   // warp's first block-col
    unsigned arow = (unsigned)(lane & 15);
    unsigned kadd = (unsigned)((lane >> 4) * 8);
    unsigned aA0 = smem_u32(xsb) + arow * (XS_STR * 2) + kadd * 2;
    unsigned aA1 = aA0 + 16 * (XS_STR * 2);
    unsigned pr   = (unsigned)(((lane >> 4) & 1) * 8 + (lane & 7));
    unsigned koff = (unsigned)(((lane >> 3) & 1) * 16);
    unsigned bl   = swzb(pr * 32 + koff);
    unsigned bbase = smem_u32(blk) + bl;
    const int d0 = a0 + 31;                   // block window start

    float acc[2][8][4] = {};

    // ---- preload j=0 fragments ----
    unsigned A0[4], A1[4], Bf[4][4];
    ldsm4(A0, aA0);
    ldsm4(A1, aA1);
#pragma unroll
    for (int r = 0; r < 4; ++r)
        ldsm4(Bf[r], bbase + (unsigned)((d0 + r) * 512));
    unsigned bPre = bbase + (unsigned)((d0 - 1) * 512);   // next-step new frag

#pragma unroll 4
    for (int j = 0; j < JSTEPS; ++j) {
        // prefetch next step (overreads land in smem pads; values unused)
        unsigned An0[4], An1[4], Bn[4];
        ldsm4(An0, aA0 + 32);
        ldsm4(An1, aA1 + 32);
        ldsm4(Bn, bPre);

        // 16 MMAs on current fragments
#pragma unroll
        for (int r = 0; r < 4; ++r) {
            mma16816(acc[0][2 * r],     A0, Bf[r][0], Bf[r][1]);
            mma16816(acc[1][2 * r],     A1, Bf[r][0], Bf[r][1]);
            mma16816(acc[0][2 * r + 1], A0, Bf[r][2], Bf[r][3]);
            mma16816(acc[1][2 * r + 1], A1, Bf[r][2], Bf[r][3]);
        }

        // rotate: window shifts by one block per k-step (circulant)
#pragma unroll
        for (int t = 0; t < 4; ++t) {
            Bf[3][t] = Bf[2][t];
            Bf[2][t] = Bf[1][t];
            Bf[1][t] = Bf[0][t];
            Bf[0][t] = Bn[t];
            A0[t] = An0[t];
            A1[t] = An1[t];
        }
        aA0 += 32; aA1 += 32;
        bPre -= 512;
    }

    // ---- epilogue: all 8 warps store f16x2 partials directly ----
    {
        const int q  = lane & 3;
        const int rw = lane >> 2;
        __half* part = g_parth + ks * PSZ;
#pragma unroll
        for (int m = 0; m < 2; ++m) {
#pragma unroll
            for (int nf = 0; nf < 8; ++nf) {
                int col = T * 512 + (a0 + (nf >> 1)) * 16 + (nf & 1) * 8 + q * 2;
                int b0  = m * 16 + rw;
                *reinterpret_cast<__half2*>(part + b0 * DIM + col) =
                    __floats2half2_rn(acc[m][nf][0], acc[m][nf][1]);
                *reinterpret_cast<__half2*>(part + (b0 + 8) * DIM + col) =
                    __floats2half2_rn(acc[m][nf][2], acc[m][nf][3]);
            }
        }
    }
}

// ---------------------------------------------------------------------------
// Kernel 2: reduce the 16 f16 partials. 32768 threads, 8 output cols each,
// 16 independent LDG.128 per thread (high MLP), f32 result.
// ---------------------------------------------------------------------------
__global__ void __launch_bounds__(256) reduce_kernel(float* __restrict__ out)
{
    int i  = blockIdx.x * 256 + threadIdx.x;  // 0..32767
    int b  = i >> 10;                         // batch row 0..31
    int cg = i & 1023;                        // col-group of 8
    int off = b * DIM + cg * 8;

    float v[8] = {};
#pragma unroll
    for (int ksp = 0; ksp < KSPLIT; ++ksp) {
        uint4 u = *reinterpret_cast<const uint4*>(g_parth + ksp * PSZ + off);
        float2 f0 = __half22float2(*reinterpret_cast<__half2*>(&u.x));
        float2 f1 = __half22float2(*reinterpret_cast<__half2*>(&u.y));
        float2 f2 = __half22float2(*reinterpret_cast<__half2*>(&u.z));
        float2 f3 = __half22float2(*reinterpret_cast<__half2*>(&u.w));
        v[0] += f0.x; v[1] += f0.y; v[2] += f1.x; v[3] += f1.y;
        v[4] += f2.x; v[5] += f2.y; v[6] += f3.x; v[7] += f3.y;
    }
    *reinterpret_cast<float4*>(out + off)     = make_float4(v[0], v[1], v[2], v[3]);
    *reinterpret_cast<float4*>(out + off + 4) = make_float4(v[4], v[5], v[6], v[7]);
}

// ---------------------------------------------------------------------------
extern "C" void kernel_launch(void* const* d_in, const int* in_sizes, int n_in,
                              void* d_out, int out_size)
{
    const float* x   = (const float*)d_in[0];
    const float* blk = (const float*)d_in[1];
    float* out = (float*)d_out;

    cudaFuncSetAttribute(bc_mma_kernel,
                         cudaFuncAttributeMaxDynamicSharedMemorySize, SMEM_TOT);

    bc_mma_kernel<<<NTILES * KSPLIT, THREADS, SMEM_TOT>>>(x, blk);
    reduce_kernel<<<128, 256>>>(out);
}

// round 12
// speedup vs baseline: 1.1271x; 1.1271x over previous
#include <cuda_runtime.h>
#include <cuda_fp16.h>

// ---------------------------------------------------------------------------
// BlocCircLinear via mma.sync m16n8k16 (f16 in / f32 acc), compute_103-safe.
//   D[b=32, 8192] = X[32, 8192] @ W^T,  W block-circulant from blocks[512][16][16].
// R12: best-proven combination.
//   - convert: f32->f16 (x + blocks), one float4/thread (lean).
//   - bc_mma: R3's proven-best kernel (256 thr, cp.async f16 staging,
//     circulant register-rotation mainloop, 128 CTAs) with f16x2 partial
//     stores (R10-proven numerics).
//   - reduce: 65536 threads (2x R10 parallelism), 4 cols/thread, MLP 8.
// ---------------------------------------------------------------------------

#define BATCH   32
#define NBLK    512
#define DIM     8192
#define NTILES  16        // 8192 / 512 output cols
#define KSPLIT  8         // K split -> 1024 per CTA
#define JSTEPS  64        // 1024 / 16
#define THREADS 256
#define PSZ     (BATCH * DIM)

#define XS_STR   1032                       // halves per x row (1024 + 8 pad)
#define BLK_N    95                         // blocks staged per CTA
#define PAD_LO   512                        // underflow pad (B prefetch d = -1)
#define PAD_HI   1024                       // overflow pad (A prefetch @ last j)
#define OFF_BLK  PAD_LO
#define OFF_XS   (PAD_LO + BLK_N * 512)     // 512 + 48640
#define SMEM_TOT (OFF_XS + BATCH * XS_STR * 2 + PAD_HI)   // 116224

__device__ __half g_xh[BATCH * DIM];        // x in f16  [32][8192]
__device__ __half g_blkh[NBLK * 256];       // blocks f16 [512][16][16]
__device__ __half g_parth[KSPLIT * PSZ];    // f16 partials [8][32][8192], 4 MB

static __device__ __forceinline__ unsigned swzb(unsigned off) {
    return off ^ ((off >> 3) & 0x70);
}
static __device__ __forceinline__ unsigned smem_u32(const void* p) {
    return (unsigned)__cvta_generic_to_shared(p);
}
static __device__ __forceinline__ void cp16(unsigned dst, const void* src) {
    asm volatile("cp.async.cg.shared.global [%0], [%1], 16;"
                 :: "r"(dst), "l"(src) : "memory");
}
static __device__ __forceinline__ void ldsm4(unsigned* r, unsigned addr) {
    asm volatile("ldmatrix.sync.aligned.m8n8.x4.shared.b16 {%0,%1,%2,%3}, [%4];"
                 : "=r"(r[0]), "=r"(r[1]), "=r"(r[2]), "=r"(r[3]) : "r"(addr));
}
static __device__ __forceinline__ void mma16816(float* c, const unsigned* a,
                                                unsigned b0, unsigned b1) {
    asm volatile(
        "mma.sync.aligned.m16n8k16.row.col.f32.f16.f16.f32 "
        "{%0,%1,%2,%3}, {%4,%5,%6,%7}, {%8,%9}, {%0,%1,%2,%3};"
        : "+f"(c[0]), "+f"(c[1]), "+f"(c[2]), "+f"(c[3])
        : "r"(a[0]), "r"(a[1]), "r"(a[2]), "r"(a[3]), "r"(b0), "r"(b1));
}

// ---------------------------------------------------------------------------
// Kernel 1: fp32 -> fp16, one float4 -> half4 per thread. 98304 threads.
// ---------------------------------------------------------------------------
__global__ void __launch_bounds__(256) convert_kernel(
    const float* __restrict__ x, const float* __restrict__ blk)
{
    int i = blockIdx.x * 256 + threadIdx.x;
    const float4* src;
    uint2* dst;
    if (i < 65536) {
        src = reinterpret_cast<const float4*>(x) + i;
        dst = reinterpret_cast<uint2*>(g_xh) + i;
    } else {
        int j = i - 65536;                    // < 32768
        src = reinterpret_cast<const float4*>(blk) + j;
        dst = reinterpret_cast<uint2*>(g_blkh) + j;
    }
    float4 a = *src;
    __half2 h0 = __float22half2_rn(make_float2(a.x, a.y));
    __half2 h1 = __float22half2_rn(make_float2(a.z, a.w));
    uint2 o;
    o.x = *reinterpret_cast<unsigned*>(&h0);
    o.y = *reinterpret_cast<unsigned*>(&h1);
    *dst = o;
}

// ---------------------------------------------------------------------------
// Kernel 2: block-circulant GEMM (R3-proven), f16x2 partial epilogue.
// grid = NTILES * KSPLIT = 128 CTAs x 256 threads.
// ---------------------------------------------------------------------------
extern __shared__ __align__(1024) char smem[];

__global__ void __launch_bounds__(THREADS, 1) bc_mma_kernel()
{
    const int tid  = threadIdx.x;
    const int wid  = tid >> 5;
    const int lane = tid & 31;
    const int T    = blockIdx.x & (NTILES - 1);
    const int ks   = blockIdx.x >> 4;
    const int smin = (T * 32 - ks * 64 - 63) & (NBLK - 1);

    char*   blk = smem + OFF_BLK;
    __half* xs  = (__half*)(smem + OFF_XS);

    // ---- stage x chunk (32 x 1024 halves) + 95 blocks via cp.async ----
    {
        const char* xsrc = (const char*)g_xh;
        for (int i = tid; i < 4096; i += THREADS) {
            int row = i >> 7, c = i & 127;
            cp16(smem_u32(xs + row * XS_STR) + c * 16,
                 xsrc + row * (DIM * 2) + ks * 2048 + c * 16);
        }
        const char* bsrc = (const char*)g_blkh;
        for (int i = tid; i < BLK_N * 32; i += THREADS) {
            int d = i >> 5, w = i & 31;
            int s = (smin + d) & (NBLK - 1);
            cp16(smem_u32(blk) + d * 512 + swzb(w * 16),
                 bsrc + s * 512 + w * 16);
        }
        asm volatile("cp.async.commit_group;\n\tcp.async.wait_group 0;" ::: "memory");
        __syncthreads();
    }

    // ---- lane-invariant ldmatrix addresses ----
    const int a0 = wid * 4;                       // warp's first block-col
    unsigned arow = (unsigned)(lane & 15);
    unsigned kadd = (unsigned)((lane >> 4) * 8);
    unsigned aA0 = smem_u32(xs) + arow * (XS_STR * 2) + kadd * 2;
    unsigned aA1 = aA0 + 16 * (XS_STR * 2);
    unsigned pr   = (unsigned)(((lane >> 4) & 1) * 8 + (lane & 7));
    unsigned koff = (unsigned)(((lane >> 3) & 1) * 16);
    unsigned bl   = swzb(pr * 32 + koff);
    unsigned bbase = smem_u32(blk) + bl;

    float acc[2][8][4] = {};

    // ---- preload j=0 fragments ----
    unsigned A0[4], A1[4], Bf[4][4];
    ldsm4(A0, aA0);
    ldsm4(A1, aA1);
#pragma unroll
    for (int r = 0; r < 4; ++r)
        ldsm4(Bf[r], bbase + (unsigned)((a0 + 63 + r) * 512));
    unsigned bPre = bbase + (unsigned)((a0 + 62) * 512);  // next-step new frag

#pragma unroll 4
    for (int j = 0; j < JSTEPS; ++j) {
        // prefetch next step (overreads land in smem pads; values unused)
        unsigned An0[4], An1[4], Bn[4];
        ldsm4(An0, aA0 + 32);
        ldsm4(An1, aA1 + 32);
        ldsm4(Bn, bPre);

        // 16 MMAs on current fragments
#pragma unroll
        for (int r = 0; r < 4; ++r) {
            mma16816(acc[0][2 * r],     A0, Bf[r][0], Bf[r][1]);
            mma16816(acc[1][2 * r],     A1, Bf[r][0], Bf[r][1]);
            mma16816(acc[0][2 * r + 1], A0, Bf[r][2], Bf[r][3]);
            mma16816(acc[1][2 * r + 1], A1, Bf[r][2], Bf[r][3]);
        }

        // rotate: window shifts by one block per k-step (circulant)
#pragma unroll
        for (int t = 0; t < 4; ++t) {
            Bf[3][t] = Bf[2][t];
            Bf[2][t] = Bf[1][t];
            Bf[1][t] = Bf[0][t];
            Bf[0][t] = Bn[t];
            A0[t] = An0[t];
            A1[t] = An1[t];
        }
        aA0 += 32; aA1 += 32;
        bPre -= 512;
    }

    // ---- epilogue: store f16x2 partials [b][col] ----
    {
        const int q  = lane & 3;
        const int rw = lane >> 2;
        __half* part = g_parth + ks * PSZ;
#pragma unroll
        for (int m = 0; m < 2; ++m) {
#pragma unroll
            for (int nf = 0; nf < 8; ++nf) {
                int col = T * 512 + (a0 + (nf >> 1)) * 16 + (nf & 1) * 8 + q * 2;
                int b0  = m * 16 + rw;
                *reinterpret_cast<__half2*>(part + b0 * DIM + col) =
                    __floats2half2_rn(acc[m][nf][0], acc[m][nf][1]);
                *reinterpret_cast<__half2*>(part + (b0 + 8) * DIM + col) =
                    __floats2half2_rn(acc[m][nf][2], acc[m][nf][3]);
            }
        }
    }
}

// ---------------------------------------------------------------------------
// Kernel 3: reduce the 8 f16 partials. 65536 threads, 4 cols each,
// 8 independent LDG.64 per thread (MLP 8), f32 result.
// ---------------------------------------------------------------------------
__global__ void __launch_bounds__(256) reduce_kernel(float* __restrict__ out)
{
    int i  = blockIdx.x * 256 + threadIdx.x;  // 0..65535
    int b  = i >> 11;                         // batch row 0..31
    int cg = i & 2047;                        // col-group of 4
    int off = b * DIM + cg * 4;

    float v[4] = {};
#pragma unroll
    for (int ksp = 0; ksp < KSPLIT; ++ksp) {
        uint2 u = *reinterpret_cast<const uint2*>(g_parth + ksp * PSZ + off);
        float2 f0 = __half22float2(*reinterpret_cast<__half2*>(&u.x));
        float2 f1 = __half22float2(*reinterpret_cast<__half2*>(&u.y));
        v[0] += f0.x; v[1] += f0.y; v[2] += f1.x; v[3] += f1.y;
    }
    *reinterpret_cast<float4*>(out + off) = make_float4(v[0], v[1], v[2], v[3]);
}

// ---------------------------------------------------------------------------
extern "C" void kernel_launch(void* const* d_in, const int* in_sizes, int n_in,
                              void* d_out, int out_size)
{
    const float* x   = (const float*)d_in[0];
    const float* blk = (const float*)d_in[1];
    float* out = (float*)d_out;

    cudaFuncSetAttribute(bc_mma_kernel,
                         cudaFuncAttributeMaxDynamicSharedMemorySize, SMEM_TOT);

    convert_kernel<<<384, 256>>>(x, blk);
    bc_mma_kernel<<<NTILES * KSPLIT, THREADS, SMEM_TOT>>>();
    reduce_kernel<<<256, 256>>>(out);
}